// round 8
// baseline (speedup 1.0000x reference)
#include <cuda_runtime.h>
#include <cuda_bf16.h>
#include <stdint.h>

namespace {

constexpr int Bb = 4, Ss = 2048, Hh = 16, Dd = 64;
constexpr int BM = 64, BN = 64;
constexpr int KP = 36;            // u32 per sK row (f16x2 words): frag bank = 4g+c, conflict-free
constexpr int VP = 72;            // u32 per sV row-pair: frag bank = 8c+g, conflict-free
constexpr float SCALE = 0.125f;   // 1/sqrt(64)
constexpr float NEGINF = -1e30f;

// pack two floats -> f16x2 (lower half = lo arg, upper half = hi arg)
__device__ __forceinline__ uint32_t packf16x2(float lo, float hi) {
    uint32_t r;
    asm("cvt.rn.f16x2.f32 %0, %1, %2;" : "=r"(r) : "f"(hi), "f"(lo));
    return r;
}

__device__ __forceinline__ void mma_f16(float c[4], const uint32_t a[4], const uint32_t b[2]) {
    asm volatile(
        "mma.sync.aligned.m16n8k16.row.col.f32.f16.f16.f32 "
        "{%0,%1,%2,%3}, {%4,%5,%6,%7}, {%8,%9}, {%0,%1,%2,%3};"
        : "+f"(c[0]), "+f"(c[1]), "+f"(c[2]), "+f"(c[3])
        : "r"(a[0]), "r"(a[1]), "r"(a[2]), "r"(a[3]), "r"(b[0]), "r"(b[1]));
}

__global__ void __launch_bounds__(128, 3)
fa_kernel(const float* __restrict__ q, const float* __restrict__ k,
          const float* __restrict__ v, const float* __restrict__ bias,
          float* __restrict__ out)
{
    __shared__ __align__(16) uint32_t sK[2][BN * KP];       // double-buffered K tile
    __shared__ __align__(16) uint32_t sV[2][(BN/2) * VP];   // double-buffered V tile

    const int tid  = threadIdx.x;
    const int lane = tid & 31;
    const int wid  = tid >> 5;
    const int g    = lane >> 2;
    const int c    = lane & 3;

    // grid: batch fastest-varying (bias L2 reuse); qt reversed (longest first)
    const int idx = blockIdx.x;
    const int b   = idx & 3;
    const int h   = (idx >> 2) & 15;
    const int qt  = (Ss / BM - 1) - (idx >> 6);
    const int qrow = qt * BM;

    const int r0 = qrow + wid * 16 + g;
    const int r1 = r0 + 8;

    // per-thread cooperative-load coordinates
    const int ldn  = tid >> 2;          // K row 0..31 handled twice (it*128+tid pattern below)
    (void)ldn;

    // ---- Q fragments (f16x2), loaded once ----
    const float* q0 = q + ((size_t)(b * Ss + r0) * Hh + h) * Dd;
    const float* q1 = q + ((size_t)(b * Ss + r1) * Hh + h) * Dd;
    uint32_t qa[4][4];
#pragma unroll
    for (int ks = 0; ks < 4; ks++) {
        const int d0 = ks * 16 + 2 * c;
        const float2 a00 = *(const float2*)(q0 + d0);
        const float2 a01 = *(const float2*)(q1 + d0);
        const float2 a10 = *(const float2*)(q0 + d0 + 8);
        const float2 a11 = *(const float2*)(q1 + d0 + 8);
        qa[ks][0] = packf16x2(a00.x, a00.y);
        qa[ks][1] = packf16x2(a01.x, a01.y);
        qa[ks][2] = packf16x2(a10.x, a10.y);
        qa[ks][3] = packf16x2(a11.x, a11.y);
    }

    float oacc[8][4];
#pragma unroll
    for (int i = 0; i < 8; i++) {
        oacc[i][0] = 0.f; oacc[i][1] = 0.f; oacc[i][2] = 0.f; oacc[i][3] = 0.f;
    }
    float m0 = NEGINF, m1 = NEGINF, l0 = 0.f, l1 = 0.f;

    const float* biasr0 = bias + ((size_t)h * Ss + r0) * Ss;
    const float* biasr1 = bias + ((size_t)h * Ss + r1) * Ss;

    // ---------- prologue: load tile 0 into buffer 0 ----------
    {
        const size_t base0 = ((size_t)(b * Ss) * Hh + h) * Dd;
        float4 kpre[8];
#pragma unroll
        for (int it = 0; it < 8; it++) {
            const int t = it * 128 + tid;
            kpre[it] = *(const float4*)(k + base0 + (size_t)(t >> 4) * (Hh * Dd) + ((t & 15) << 2));
        }
#pragma unroll
        for (int it = 0; it < 8; it++) {
            const int t = it * 128 + tid;
            uint2 kt;
            kt.x = packf16x2(kpre[it].x, kpre[it].y);
            kt.y = packf16x2(kpre[it].z, kpre[it].w);
            *(uint2*)(&sK[0][(t >> 4) * KP + (((t & 15) << 2) >> 1)]) = kt;
        }
        float4 vp0[4], vp1[4];
#pragma unroll
        for (int it = 0; it < 4; it++) {
            const int t = it * 128 + tid;
            const float* vb = v + base0 + (size_t)(2 * (t >> 4)) * (Hh * Dd) + ((t & 15) << 2);
            vp0[it] = *(const float4*)(vb);
            vp1[it] = *(const float4*)(vb + Hh * Dd);
        }
#pragma unroll
        for (int it = 0; it < 4; it++) {
            const int t = it * 128 + tid;
            uint4 hi;
            hi.x = packf16x2(vp0[it].x, vp1[it].x);
            hi.y = packf16x2(vp0[it].y, vp1[it].y);
            hi.z = packf16x2(vp0[it].z, vp1[it].z);
            hi.w = packf16x2(vp0[it].w, vp1[it].w);
            *(uint4*)(&sV[0][(t >> 4) * VP + ((t & 15) << 2)]) = hi;
        }
    }
    __syncthreads();

    for (int j = 0; j <= qt; j++) {
        const int p  = j & 1;
        const int jn = (j < qt) ? (j + 1) : j;   // clamped prefetch tile
        const size_t basen = ((size_t)(b * Ss + jn * BN) * Hh + h) * Dd;

        // ===== phase A: issue bias LDG for tile j, then QK mma =====
        const int kcb = j * BN;
        float2 bpre0[8], bpre1[8];
#pragma unroll
        for (int nf = 0; nf < 8; nf++) {
            const int kc = kcb + nf * 8 + 2 * c;
            bpre0[nf] = __ldg((const float2*)(biasr0 + kc));
            bpre1[nf] = __ldg((const float2*)(biasr1 + kc));
        }

        float sacc[8][4];
#pragma unroll
        for (int nf = 0; nf < 8; nf++) {
            sacc[nf][0] = 0.f; sacc[nf][1] = 0.f; sacc[nf][2] = 0.f; sacc[nf][3] = 0.f;
#pragma unroll
            for (int ks = 0; ks < 4; ks++) {
                const uint32_t* kp = &sK[p][(nf * 8 + g) * KP + ks * 8 + c];
                uint32_t bfr[2];
                bfr[0] = kp[0];
                bfr[1] = kp[4];
                mma_f16(sacc[nf], qa[ks], bfr);
            }
        }

        // scale + bias + causal mask
        const bool diag = (j == qt);
#pragma unroll
        for (int nf = 0; nf < 8; nf++) {
            const int kc = kcb + nf * 8 + 2 * c;
            sacc[nf][0] = sacc[nf][0] * SCALE + bpre0[nf].x;
            sacc[nf][1] = sacc[nf][1] * SCALE + bpre0[nf].y;
            sacc[nf][2] = sacc[nf][2] * SCALE + bpre1[nf].x;
            sacc[nf][3] = sacc[nf][3] * SCALE + bpre1[nf].y;
            if (diag) {
                if (kc     > r0) sacc[nf][0] = NEGINF;
                if (kc + 1 > r0) sacc[nf][1] = NEGINF;
                if (kc     > r1) sacc[nf][2] = NEGINF;
                if (kc + 1 > r1) sacc[nf][3] = NEGINF;
            }
        }

        // ===== phase B: issue K LDG for j+1, softmax covers latency =====
        float4 kpre[8];
#pragma unroll
        for (int it = 0; it < 8; it++) {
            const int t = it * 128 + tid;
            kpre[it] = *(const float4*)(k + basen + (size_t)(t >> 4) * (Hh * Dd) + ((t & 15) << 2));
        }

        float rm0 = NEGINF, rm1 = NEGINF;
#pragma unroll
        for (int nf = 0; nf < 8; nf++) {
            rm0 = fmaxf(rm0, fmaxf(sacc[nf][0], sacc[nf][1]));
            rm1 = fmaxf(rm1, fmaxf(sacc[nf][2], sacc[nf][3]));
        }
        rm0 = fmaxf(rm0, __shfl_xor_sync(0xffffffffu, rm0, 1));
        rm0 = fmaxf(rm0, __shfl_xor_sync(0xffffffffu, rm0, 2));
        rm1 = fmaxf(rm1, __shfl_xor_sync(0xffffffffu, rm1, 1));
        rm1 = fmaxf(rm1, __shfl_xor_sync(0xffffffffu, rm1, 2));

        const float nm0 = fmaxf(m0, rm0), nm1 = fmaxf(m1, rm1);
        const float a0 = __expf(m0 - nm0), a1 = __expf(m1 - nm1);
        m0 = nm0; m1 = nm1;

        float rs0 = 0.f, rs1 = 0.f;
#pragma unroll
        for (int nf = 0; nf < 8; nf++) {
            sacc[nf][0] = __expf(sacc[nf][0] - nm0);
            sacc[nf][1] = __expf(sacc[nf][1] - nm0);
            sacc[nf][2] = __expf(sacc[nf][2] - nm1);
            sacc[nf][3] = __expf(sacc[nf][3] - nm1);
            rs0 += sacc[nf][0] + sacc[nf][1];
            rs1 += sacc[nf][2] + sacc[nf][3];
        }
        l0 = l0 * a0 + rs0;
        l1 = l1 * a1 + rs1;

#pragma unroll
        for (int df = 0; df < 8; df++) {
            oacc[df][0] *= a0; oacc[df][1] *= a0;
            oacc[df][2] *= a1; oacc[df][3] *= a1;
        }

        // store prefetched K into the other buffer
#pragma unroll
        for (int it = 0; it < 8; it++) {
            const int t = it * 128 + tid;
            uint2 kt;
            kt.x = packf16x2(kpre[it].x, kpre[it].y);
            kt.y = packf16x2(kpre[it].z, kpre[it].w);
            *(uint2*)(&sK[p ^ 1][(t >> 4) * KP + (((t & 15) << 2) >> 1)]) = kt;
        }

        // ===== phase C: issue V LDG for j+1, PV mma covers latency =====
        float4 vp0[4], vp1[4];
#pragma unroll
        for (int it = 0; it < 4; it++) {
            const int t = it * 128 + tid;
            const float* vb = v + basen + (size_t)(2 * (t >> 4)) * (Hh * Dd) + ((t & 15) << 2);
            vp0[it] = *(const float4*)(vb);
            vp1[it] = *(const float4*)(vb + Hh * Dd);
        }

#pragma unroll
        for (int t = 0; t < 4; t++) {
            uint32_t af[4];
            af[0] = packf16x2(sacc[2 * t][0],     sacc[2 * t][1]);
            af[1] = packf16x2(sacc[2 * t][2],     sacc[2 * t][3]);
            af[2] = packf16x2(sacc[2 * t + 1][0], sacc[2 * t + 1][1]);
            af[3] = packf16x2(sacc[2 * t + 1][2], sacc[2 * t + 1][3]);
            const int rpb = t * 8 + c;
#pragma unroll
            for (int df = 0; df < 8; df++) {
                const uint32_t* vh = &sV[p][rpb * VP + df * 8 + g];
                uint32_t bfr[2];
                bfr[0] = vh[0];
                bfr[1] = vh[4 * VP];
                mma_f16(oacc[df], af, bfr);
            }
        }

        // store prefetched V into the other buffer
#pragma unroll
        for (int it = 0; it < 4; it++) {
            const int t = it * 128 + tid;
            uint4 hi;
            hi.x = packf16x2(vp0[it].x, vp1[it].x);
            hi.y = packf16x2(vp0[it].y, vp1[it].y);
            hi.z = packf16x2(vp0[it].z, vp1[it].z);
            hi.w = packf16x2(vp0[it].w, vp1[it].w);
            *(uint4*)(&sV[p ^ 1][(t >> 4) * VP + ((t & 15) << 2)]) = hi;
        }

        __syncthreads();   // single barrier per tile
    }

    // ---- epilogue: finish l reduction, normalize, store ----
    l0 += __shfl_xor_sync(0xffffffffu, l0, 1);
    l0 += __shfl_xor_sync(0xffffffffu, l0, 2);
    l1 += __shfl_xor_sync(0xffffffffu, l1, 1);
    l1 += __shfl_xor_sync(0xffffffffu, l1, 2);
    const float inv0 = 1.0f / l0;
    const float inv1 = 1.0f / l1;

    float* o0 = out + ((size_t)(b * Ss + r0) * Hh + h) * Dd;
    float* o1 = out + ((size_t)(b * Ss + r1) * Hh + h) * Dd;
#pragma unroll
    for (int df = 0; df < 8; df++) {
        const int dc = df * 8 + 2 * c;
        float2 w0, w1;
        w0.x = oacc[df][0] * inv0; w0.y = oacc[df][1] * inv0;
        w1.x = oacc[df][2] * inv1; w1.y = oacc[df][3] * inv1;
        *(float2*)(o0 + dc) = w0;
        *(float2*)(o1 + dc) = w1;
    }
}

} // namespace

extern "C" void kernel_launch(void* const* d_in, const int* in_sizes, int n_in,
                              void* d_out, int out_size)
{
    const float* q    = (const float*)d_in[0];
    const float* k    = (const float*)d_in[1];
    const float* v    = (const float*)d_in[2];
    const float* bias = (const float*)d_in[3];
    float* out        = (float*)d_out;

    const dim3 grid(Bb * Hh * (Ss / BM));  // 2048 CTAs, batch fastest-varying
    fa_kernel<<<grid, 128>>>(q, k, v, bias, out);
}

// round 9
// speedup vs baseline: 1.0928x; 1.0928x over previous
#include <cuda_runtime.h>
#include <cuda_bf16.h>
#include <stdint.h>

namespace {

constexpr int Bb = 4, Ss = 2048, Hh = 16, Dd = 64;
constexpr int BM = 64, BN = 64;
constexpr int KP = 36;            // u32 per sK row (f16x2 words): frag bank = 4g+c, conflict-free
constexpr int VP = 72;            // u32 per sV row-pair: frag bank = 8c+g, conflict-free
constexpr float SCALE = 0.125f;   // 1/sqrt(64)
constexpr float LOG2E = 1.4426950408889634f;
constexpr float NEGINF = -1e30f;

// pack two floats -> f16x2 (lower half = lo arg, upper half = hi arg)
__device__ __forceinline__ uint32_t packf16x2(float lo, float hi) {
    uint32_t r;
    asm("cvt.rn.f16x2.f32 %0, %1, %2;" : "=r"(r) : "f"(hi), "f"(lo));
    return r;
}
// paired fp16 exp2
__device__ __forceinline__ uint32_t ex2h2(uint32_t x) {
    uint32_t r;
    asm("ex2.approx.f16x2 %0, %1;" : "=r"(r) : "r"(x));
    return r;
}

__device__ __forceinline__ void mma_f16(float c[4], const uint32_t a[4], const uint32_t b[2]) {
    asm volatile(
        "mma.sync.aligned.m16n8k16.row.col.f32.f16.f16.f32 "
        "{%0,%1,%2,%3}, {%4,%5,%6,%7}, {%8,%9}, {%0,%1,%2,%3};"
        : "+f"(c[0]), "+f"(c[1]), "+f"(c[2]), "+f"(c[3])
        : "r"(a[0]), "r"(a[1]), "r"(a[2]), "r"(a[3]), "r"(b[0]), "r"(b[1]));
}

__global__ void __launch_bounds__(128, 3)
fa_kernel(const float* __restrict__ q, const float* __restrict__ k,
          const float* __restrict__ v, const float* __restrict__ bias,
          float* __restrict__ out)
{
    __shared__ __align__(16) uint32_t sK[BN * KP];       // K tile, f16x2 d-pairs, [n][d/2]
    __shared__ __align__(16) uint32_t sV[(BN/2) * VP];   // V tile, f16x2 seq row-pairs

    const int tid  = threadIdx.x;
    const int lane = tid & 31;
    const int wid  = tid >> 5;
    const int g    = lane >> 2;
    const int c    = lane & 3;

    // grid: batch fastest-varying (bias L2 reuse); qt reversed (longest first)
    const int idx = blockIdx.x;
    const int b   = idx & 3;
    const int h   = (idx >> 2) & 15;
    const int qt  = (Ss / BM - 1) - (idx >> 6);
    const int qrow = qt * BM;

    const int r0 = qrow + wid * 16 + g;
    const int r1 = r0 + 8;

    // ---- Q fragments (f16x2), loaded once ----
    const float* q0 = q + ((size_t)(b * Ss + r0) * Hh + h) * Dd;
    const float* q1 = q + ((size_t)(b * Ss + r1) * Hh + h) * Dd;
    uint32_t qa[4][4];
#pragma unroll
    for (int ks = 0; ks < 4; ks++) {
        const int d0 = ks * 16 + 2 * c;
        const float2 a00 = *(const float2*)(q0 + d0);
        const float2 a01 = *(const float2*)(q1 + d0);
        const float2 a10 = *(const float2*)(q0 + d0 + 8);
        const float2 a11 = *(const float2*)(q1 + d0 + 8);
        qa[ks][0] = packf16x2(a00.x, a00.y);
        qa[ks][1] = packf16x2(a01.x, a01.y);
        qa[ks][2] = packf16x2(a10.x, a10.y);
        qa[ks][3] = packf16x2(a11.x, a11.y);
    }

    float oacc[8][4];
#pragma unroll
    for (int i = 0; i < 8; i++) {
        oacc[i][0] = 0.f; oacc[i][1] = 0.f; oacc[i][2] = 0.f; oacc[i][3] = 0.f;
    }
    float lacc[4] = {0.f, 0.f, 0.f, 0.f};   // row-sum accumulator (ones-column mma)
    float m0 = NEGINF, m1 = NEGINF;

    // ones-column B fragment for row-sum mma: column n=0 only (lanes g==0)
    const uint32_t onesw = (g == 0) ? 0x3C003C00u : 0u;
    const uint32_t onesb[2] = {onesw, onesw};

    const float* biasr0 = bias + ((size_t)h * Ss + r0) * Ss;
    const float* biasr1 = bias + ((size_t)h * Ss + r1) * Ss;

    for (int j = 0; j <= qt; j++) {
        __syncthreads();
        const size_t base = ((size_t)(b * Ss + j * BN) * Hh + h) * Dd;

        // ---- K tile: fp32 -> f16x2 d-pairs -> smem ----
#pragma unroll
        for (int it = 0; it < 8; it++) {
            const int t  = it * 128 + tid;
            const int n  = t >> 4;
            const int d4 = (t & 15) << 2;
            const float4 kv = *(const float4*)(k + base + (size_t)n * (Hh * Dd) + d4);
            uint2 kt;
            kt.x = packf16x2(kv.x, kv.y);
            kt.y = packf16x2(kv.z, kv.w);
            *(uint2*)(&sK[n * KP + (d4 >> 1)]) = kt;
        }
        // ---- V tile: fp32 seq row-pairs -> f16x2 -> smem ----
#pragma unroll
        for (int it = 0; it < 4; it++) {
            const int t  = it * 128 + tid;
            const int rp = t >> 4;
            const int d4 = (t & 15) << 2;
            const float* vb = v + base + (size_t)(2 * rp) * (Hh * Dd) + d4;
            const float4 v0 = *(const float4*)(vb);
            const float4 v1 = *(const float4*)(vb + Hh * Dd);
            uint4 hi;
            hi.x = packf16x2(v0.x, v1.x);
            hi.y = packf16x2(v0.y, v1.y);
            hi.z = packf16x2(v0.z, v1.z);
            hi.w = packf16x2(v0.w, v1.w);
            *(uint4*)(&sV[rp * VP + d4]) = hi;
        }
        __syncthreads();

        // ---- S = Q K^T (fp16 m16n8k16 mma) ----
        float sacc[8][4];
#pragma unroll
        for (int nf = 0; nf < 8; nf++) {
            sacc[nf][0] = 0.f; sacc[nf][1] = 0.f; sacc[nf][2] = 0.f; sacc[nf][3] = 0.f;
#pragma unroll
            for (int ks = 0; ks < 4; ks++) {
                const uint32_t* kp = &sK[(nf * 8 + g) * KP + ks * 8 + c];
                uint32_t bfr[2];
                bfr[0] = kp[0];
                bfr[1] = kp[4];
                mma_f16(sacc[nf], qa[ks], bfr);
            }
        }

        // ---- scale + bias + causal mask ----
        const int kcb = j * BN;
        const bool diag = (j == qt);
#pragma unroll
        for (int nf = 0; nf < 8; nf++) {
            const int kc = kcb + nf * 8 + 2 * c;
            const float2 bb0 = __ldg((const float2*)(biasr0 + kc));
            const float2 bb1 = __ldg((const float2*)(biasr1 + kc));
            sacc[nf][0] = sacc[nf][0] * SCALE + bb0.x;
            sacc[nf][1] = sacc[nf][1] * SCALE + bb0.y;
            sacc[nf][2] = sacc[nf][2] * SCALE + bb1.x;
            sacc[nf][3] = sacc[nf][3] * SCALE + bb1.y;
            if (diag) {
                if (kc     > r0) sacc[nf][0] = NEGINF;
                if (kc + 1 > r0) sacc[nf][1] = NEGINF;
                if (kc     > r1) sacc[nf][2] = NEGINF;
                if (kc + 1 > r1) sacc[nf][3] = NEGINF;
            }
        }

        // ---- online softmax: max only (sums come from ones-column mma) ----
        float rm0 = NEGINF, rm1 = NEGINF;
#pragma unroll
        for (int nf = 0; nf < 8; nf++) {
            rm0 = fmaxf(rm0, fmaxf(sacc[nf][0], sacc[nf][1]));
            rm1 = fmaxf(rm1, fmaxf(sacc[nf][2], sacc[nf][3]));
        }
        rm0 = fmaxf(rm0, __shfl_xor_sync(0xffffffffu, rm0, 1));
        rm0 = fmaxf(rm0, __shfl_xor_sync(0xffffffffu, rm0, 2));
        rm1 = fmaxf(rm1, __shfl_xor_sync(0xffffffffu, rm1, 1));
        rm1 = fmaxf(rm1, __shfl_xor_sync(0xffffffffu, rm1, 2));

        const float nm0 = fmaxf(m0, rm0), nm1 = fmaxf(m1, rm1);
        const float a0 = __expf(m0 - nm0), a1 = __expf(m1 - nm1);
        m0 = nm0; m1 = nm1;
        const float mL0 = nm0 * LOG2E, mL1 = nm1 * LOG2E;

        lacc[0] *= a0; lacc[1] *= a0; lacc[2] *= a1; lacc[3] *= a1;
#pragma unroll
        for (int df = 0; df < 8; df++) {
            oacc[df][0] *= a0; oacc[df][1] *= a0;
            oacc[df][2] *= a1; oacc[df][3] *= a1;
        }

        // ---- P = ex2(s*log2e - m*log2e) packed fp16; O += P V; l += P·1 ----
#pragma unroll
        for (int t = 0; t < 4; t++) {
            uint32_t af[4];
            af[0] = ex2h2(packf16x2(fmaf(sacc[2*t][0],   LOG2E, -mL0),
                                    fmaf(sacc[2*t][1],   LOG2E, -mL0)));
            af[1] = ex2h2(packf16x2(fmaf(sacc[2*t][2],   LOG2E, -mL1),
                                    fmaf(sacc[2*t][3],   LOG2E, -mL1)));
            af[2] = ex2h2(packf16x2(fmaf(sacc[2*t+1][0], LOG2E, -mL0),
                                    fmaf(sacc[2*t+1][1], LOG2E, -mL0)));
            af[3] = ex2h2(packf16x2(fmaf(sacc[2*t+1][2], LOG2E, -mL1),
                                    fmaf(sacc[2*t+1][3], LOG2E, -mL1)));

            mma_f16(lacc, af, onesb);   // row sums into column 0

            const int rpb = t * 8 + c;
#pragma unroll
            for (int df = 0; df < 8; df++) {
                const uint32_t* vh = &sV[rpb * VP + df * 8 + g];
                uint32_t bfr[2];
                bfr[0] = vh[0];
                bfr[1] = vh[4 * VP];
                mma_f16(oacc[df], af, bfr);
            }
        }
    }

    // ---- epilogue: broadcast row sums (live in lanes c==0), normalize, store ----
    const float l0 = __shfl_sync(0xffffffffu, lacc[0], lane & ~3);
    const float l1 = __shfl_sync(0xffffffffu, lacc[2], lane & ~3);
    const float inv0 = 1.0f / l0;
    const float inv1 = 1.0f / l1;

    float* o0 = out + ((size_t)(b * Ss + r0) * Hh + h) * Dd;
    float* o1 = out + ((size_t)(b * Ss + r1) * Hh + h) * Dd;
#pragma unroll
    for (int df = 0; df < 8; df++) {
        const int dc = df * 8 + 2 * c;
        float2 w0, w1;
        w0.x = oacc[df][0] * inv0; w0.y = oacc[df][1] * inv0;
        w1.x = oacc[df][2] * inv1; w1.y = oacc[df][3] * inv1;
        *(float2*)(o0 + dc) = w0;
        *(float2*)(o1 + dc) = w1;
    }
}

} // namespace

extern "C" void kernel_launch(void* const* d_in, const int* in_sizes, int n_in,
                              void* d_out, int out_size)
{
    const float* q    = (const float*)d_in[0];
    const float* k    = (const float*)d_in[1];
    const float* v    = (const float*)d_in[2];
    const float* bias = (const float*)d_in[3];
    float* out        = (float*)d_out;

    const dim3 grid(Bb * Hh * (Ss / BM));  // 2048 CTAs, batch fastest-varying
    fa_kernel<<<grid, 128>>>(q, k, v, bias, out);
}